// round 13
// baseline (speedup 1.0000x reference)
#include <cuda_runtime.h>
#include <cuda_bf16.h>
#include <math.h>
#include <stdint.h>

#define F_N   10000
#define H_N   64
#define G_N   (4 * H_N)          // 256 gate rows
#define IN_N  (H_N + 1)          // 65
#define W_ELEMS (G_N * IN_N)     // 16640 floats
#define OUT_PRED_OFF 0
#define OUT_H_OFF    2
#define OUT_C_OFF    (2 + F_N * H_N)

#define GRID_C 148
#define NSTAGE 3
#define MAXNF  68                // max features per CTA

// per-stage float offsets (R6 layout — proven fastest)
#define W_OFF     0
#define BIAS_OFF  (W_ELEMS)                  // 16640  (256 floats)
#define HT_OFF    (BIAS_OFF + G_N)           // 16896  (64) -> 16B aligned
#define XTW_OFF   (HT_OFF + H_N)             // 16960
#define XTB_OFF   (XTW_OFF + H_N)            // 17024
#define DELT_OFF  (XTB_OFF + H_N)            // 17088  (128)
#define CIN_OFF   (DELT_OFF + 2 * H_N)       // 17216
#define CF_OFF    (CIN_OFF + H_N)            // 17280
#define COUT_OFF  (CF_OFF + H_N)             // 17344
#define STAGE_F   (COUT_OFF + H_N)           // 17408 floats = 69632 B
#define STAGE_B   (STAGE_F * 4)

#define ISSUER_TID 224           // warp 7 lane 0: NOT in elementwise (tid<64)

__device__ float g_sumC[H_N];    // zero at module load; last CTA re-zeros
__device__ float g_sumH[H_N];
__device__ int   g_cnt;          // total active; written by compact_kernel
__device__ unsigned int g_done;
__device__ int   g_list[F_N];    // compacted active feature indices

__device__ __forceinline__ float sigmoidf_(float x) {
    return 1.0f / (1.0f + expf(-x));
}

__device__ __forceinline__ uint32_t smem_u32(const void* p) {
    uint32_t a;
    asm("{ .reg .u64 t; cvta.to.shared.u64 t, %1; cvt.u32.u64 %0, t; }"
        : "=r"(a) : "l"(p));
    return a;
}

__device__ __forceinline__ void mbar_init(uint32_t mbar, uint32_t cnt) {
    asm volatile("mbarrier.init.shared.b64 [%0], %1;" :: "r"(mbar), "r"(cnt) : "memory");
}
__device__ __forceinline__ void mbar_expect_tx(uint32_t mbar, uint32_t bytes) {
    asm volatile("mbarrier.arrive.expect_tx.shared.b64 _, [%0], %1;"
                 :: "r"(mbar), "r"(bytes) : "memory");
}
__device__ __forceinline__ void mbar_wait(uint32_t mbar, uint32_t parity) {
    uint32_t done;
    asm volatile(
        "{\n\t.reg .pred p;\n\t"
        "mbarrier.try_wait.parity.acquire.cta.shared::cta.b64 p, [%1], %2;\n\t"
        "selp.b32 %0, 1, 0, p;\n\t}"
        : "=r"(done) : "r"(mbar), "r"(parity) : "memory");
    if (!done) {
        asm volatile(
            "{\n\t.reg .pred P1;\n\t"
            "W_%=:\n\t"
            "mbarrier.try_wait.parity.acquire.cta.shared::cta.b64 P1, [%0], %1, 0x989680;\n\t"
            "@P1 bra.uni D_%=;\n\t"
            "bra.uni W_%=;\n\t"
            "D_%=:\n\t}"
            :: "r"(mbar), "r"(parity) : "memory");
    }
}
__device__ __forceinline__ void bulk_cp(uint32_t dst, const void* src,
                                        uint32_t bytes, uint32_t mbar) {
    asm volatile(
        "cp.async.bulk.shared::cta.global.mbarrier::complete_tx::bytes [%0], [%1], %2, [%3];"
        :: "r"(dst), "l"(src), "r"(bytes), "r"(mbar) : "memory");
}
__device__ __forceinline__ void stcs(float* p, float v) {
    asm volatile("st.global.cs.f32 [%0], %1;" :: "l"(p), "f"(v) : "memory");
}

// ---- order-preserving mask compaction: g_list, g_cnt ----
__global__ __launch_bounds__(1024) void compact_kernel(const int* __restrict__ mask) {
    __shared__ int s_cnt[1024];
    const int tid = threadIdx.x;
    const int per = (F_N + 1023) / 1024;      // 10
    const int base = tid * per;
    int idx[10];
    int c = 0;
    #pragma unroll
    for (int i = 0; i < per; i++) {
        const int g = base + i;
        if (g < F_N && mask[g] == 1) idx[c++] = g;
    }
    s_cnt[tid] = c;
    __syncthreads();
    for (int o = 1; o < 1024; o <<= 1) {
        const int v = (tid >= o) ? s_cnt[tid - o] : 0;
        __syncthreads();
        s_cnt[tid] += v;
        __syncthreads();
    }
    const int off = s_cnt[tid] - c;           // exclusive prefix
    for (int i = 0; i < c; i++) g_list[off + i] = idx[i];
    if (tid == 1023) g_cnt = s_cnt[1023];
}

__global__ __launch_bounds__(256, 1) void cell_kernel(
    const int*  __restrict__ tim_p,
    const float* __restrict__ X,
    const int*  __restrict__ mask,
    const int*  __restrict__ last_occ,
    const float* __restrict__ Ht,
    const float* __restrict__ c_t,
    const float* __restrict__ W,       // [F, 256, 65]
    const float* __restrict__ Bias,    // [F, 256]
    const float* __restrict__ xTw,     // [F, 64]
    const float* __restrict__ xTb,     // [F, 64]
    const float* __restrict__ delTw,   // [F, 128]
    const float* __restrict__ cinw,    // [F, 64]
    const float* __restrict__ cfw,     // [F, 64]
    const float* __restrict__ coutw,   // [F, 64]
    const float* __restrict__ w1,      // [128,128]
    const float* __restrict__ b1,      // [128]
    const float* __restrict__ w2,      // [2,128]
    const float* __restrict__ b2,      // [2]
    float* __restrict__ out)
{
    extern __shared__ float s_buf[];           // NSTAGE * STAGE_F floats
    __shared__ float s_gates[G_N];
    __shared__ float s_ct[H_N];
    __shared__ int   s_f[MAXNF];
    __shared__ float s_X[MAXNF];
    __shared__ float s_delta[MAXNF];
    __shared__ __align__(8) uint64_t s_mbar[NSTAGE];
    __shared__ int s_last;

    const int bid = blockIdx.x;
    const int tid = threadIdx.x;
    const int total = g_cnt;                               // from compact_kernel
    const int na = (total > bid) ? ((total - bid - 1) / GRID_C + 1) : 0;

    // ---- prologue: barriers, gather active features ----
    if (tid == 0) {
        for (int s = 0; s < NSTAGE; s++) mbar_init(smem_u32(&s_mbar[s]), 1);
        asm volatile("fence.proxy.async.shared::cta;" ::: "memory");
    }
    {
        const int tim = *tim_p;
        if (tid < na) {                                    // na <= 68 < 256
            const int f = g_list[bid + tid * GRID_C];
            s_f[tid]     = f;
            s_X[tid]     = X[f];
            s_delta[tid] = (float)tim - (float)last_occ[f];
        }
    }
    if (tid < H_N) s_ct[tid] = c_t[tid];
    __syncthreads();                       // mbars + s_f visible

    const uint32_t sbase = smem_u32(s_buf);

    auto issue = [&](int j) {
        const int s = j % NSTAGE;
        const size_t f = (size_t)s_f[j];
        const uint32_t d = sbase + (uint32_t)s * STAGE_B;
        const uint32_t mb = smem_u32(&s_mbar[s]);
        mbar_expect_tx(mb, STAGE_B);
        bulk_cp(d + W_OFF * 4,    W     + f * W_ELEMS,   W_ELEMS * 4, mb);
        bulk_cp(d + BIAS_OFF * 4, Bias  + f * G_N,       G_N * 4,     mb);
        bulk_cp(d + HT_OFF * 4,   Ht    + f * H_N,       H_N * 4,     mb);
        bulk_cp(d + XTW_OFF * 4,  xTw   + f * H_N,       H_N * 4,     mb);
        bulk_cp(d + XTB_OFF * 4,  xTb   + f * H_N,       H_N * 4,     mb);
        bulk_cp(d + DELT_OFF * 4, delTw + f * 2 * H_N,   2 * H_N * 4, mb);
        bulk_cp(d + CIN_OFF * 4,  cinw  + f * H_N,       H_N * 4,     mb);
        bulk_cp(d + CF_OFF * 4,   cfw   + f * H_N,       H_N * 4,     mb);
        bulk_cp(d + COUT_OFF * 4, coutw + f * H_N,       H_N * 4,     mb);
    };

    // start the pipeline BEFORE the zero-writes (overlap them with the fill)
    if (tid == ISSUER_TID) {
        const int pre = (na < NSTAGE) ? na : NSTAGE;
        for (int j = 0; j < pre; j++) issue(j);
    }

    // inactive rows of this CTA's static partition -> zeros (or Ht if total==0)
    {
        const int nf_static = (F_N - bid + GRID_C - 1) / GRID_C;
        if (tid < nf_static) {
            const int f = bid + tid * GRID_C;
            if (mask[f] != 1) {
                float* dst = out + OUT_H_OFF + (size_t)f * H_N;
                if (total == 0) {          // reference fallback: H_curr = Ht
                    const float* src = Ht + (size_t)f * H_N;
                    #pragma unroll
                    for (int q = 0; q < H_N; q++) stcs(&dst[q], src[q]);
                } else {
                    #pragma unroll
                    for (int q = 0; q < H_N; q++) stcs(&dst[q], 0.0f);
                }
            }
        }
    }

    // ---- main loop over ACTIVE features only ----
    for (int j = 0; j < na; j++) {
        const int s  = j % NSTAGE;
        const int ph = (j / NSTAGE) & 1;
        mbar_wait(smem_u32(&s_mbar[s]), ph);

        const float* buf = s_buf + (size_t)s * STAGE_F;

        // gates: one row/thread; stride-65 conflict-free + float4 broadcasts
        {
            const float  xv  = s_X[j];
            const float* row = buf + tid * IN_N;
            const float4* ht4 = (const float4*)(buf + HT_OFF);
            float acc = row[0] * xv;
            #pragma unroll
            for (int c = 0; c < 16; c++) {
                const float4 h4 = ht4[c];
                acc += row[1 + 4 * c] * h4.x;
                acc += row[2 + 4 * c] * h4.y;
                acc += row[3 + 4 * c] * h4.z;
                acc += row[4 + 4 * c] * h4.w;
            }
            s_gates[tid] = acc + buf[BIAS_OFF + tid];
        }

        // small params -> regs before the barrier (stage consumed at barrier)
        float p_cin = 0.f, p_cf = 0.f, p_cout = 0.f;
        float p_xtw = 0.f, p_xtb = 0.f, p_dtt = 0.f, p_dto = 0.f;
        if (tid < H_N) {
            p_cin  = buf[CIN_OFF + tid];
            p_cf   = buf[CF_OFF + tid];
            p_cout = buf[COUT_OFF + tid];
            p_xtw  = buf[XTW_OFF + tid];
            p_xtb  = buf[XTB_OFF + tid];
            p_dtt  = buf[DELT_OFF + tid];
            p_dto  = buf[DELT_OFF + H_N + tid];
        }
        __syncthreads();      // stage s fully consumed; gates visible

        // refill from warp 7 — runs CONCURRENTLY with the elementwise below
        if (tid == ISSUER_TID && j + NSTAGE < na) issue(j + NSTAGE);

        if (tid < H_N) {
            const int h = tid;
            const int f = s_f[j];
            const float ct    = s_ct[h];
            const float delta = s_delta[j];

            const float gi     = sigmoidf_(s_gates[h]           + p_cin * ct);
            const float gf     = sigmoidf_(s_gates[H_N + h]     + p_cf  * ct);
            const float go_pre = s_gates[2 * H_N + h];
            const float pre_c  = tanhf(s_gates[3 * H_N + h]);

            const float xmT = p_xtw * s_X[j] + p_xtb;
            const float Tt  = sigmoidf_(xmT + p_dtt * delta);

            const float aggc = gf * ct + gi * Tt * pre_c;
            const float go   = sigmoidf_(go_pre + p_cout * aggc + p_dto * delta);
            const float hn   = go * tanhf(aggc);

            stcs(&out[OUT_H_OFF + (size_t)f * H_N + h], hn);   // mf == 1 here
            atomicAdd(&g_sumC[h], aggc);
            atomicAdd(&g_sumH[h], hn);
        }
        __syncthreads();      // s_gates WAR protection for next iteration
    }

    // ---- last-CTA-done: fused MLP head ----
    __threadfence();
    if (tid == 0) {
        const unsigned prev = atomicAdd(&g_done, 1u);
        s_last = (prev == GRID_C - 1u) ? 1 : 0;
    }
    __syncthreads();
    if (!s_last) return;
    __threadfence();                    // acquire: see all CTAs' atomics

    // reuse stage smem for head scratch
    float* s_inp  = s_buf;              // 128
    float* s_part = s_buf + 128;        // 256
    float* s_hid  = s_buf + 128 + 256;  // 128
    float* s_log  = s_buf + 128 + 256 + 128; // 2

    const float cnt = fmaxf((float)total, 1.0f);
    if (tid < 2 * H_N) {
        const float v = ((tid < H_N) ? g_sumC[tid] : g_sumH[tid - H_N]) / cnt;
        s_inp[tid] = v;
        if (tid < H_N) out[OUT_C_OFF + tid] = v;
    }
    __syncthreads();

    // re-zero device accumulators for next graph replay
    if (tid < H_N) { g_sumC[tid] = 0.0f; g_sumH[tid] = 0.0f; }
    if (tid == H_N) g_done = 0u;

    // hidden: 2 threads per row, 16 float4 LDGs each
    {
        const int r = tid >> 1;
        const int g = tid & 1;
        const float4* wrow = (const float4*)(w1 + r * 2 * H_N) + g * 16;
        const float4* in4  = (const float4*)s_inp + g * 16;
        float acc = 0.0f;
        #pragma unroll
        for (int q = 0; q < 16; q++) {
            const float4 w4 = wrow[q];
            const float4 i4 = in4[q];
            acc += w4.x * i4.x + w4.y * i4.y + w4.z * i4.z + w4.w * i4.w;
        }
        s_part[tid] = acc;
    }
    __syncthreads();

    if (tid < 2 * H_N)
        s_hid[tid] = fmaxf(s_part[2 * tid] + s_part[2 * tid + 1] + b1[tid], 0.0f);
    __syncthreads();

    // logits: warp 0 -> class 0, warp 1 -> class 1
    if (tid < 64) {
        const int cls  = tid >> 5;
        const int lane = tid & 31;
        const float4 w4a = ((const float4*)(w2 + cls * 2 * H_N))[lane];
        const float* hp = s_hid + lane * 4;
        float acc = w4a.x * hp[0] + w4a.y * hp[1] + w4a.z * hp[2] + w4a.w * hp[3];
        #pragma unroll
        for (int o = 16; o > 0; o >>= 1)
            acc += __shfl_xor_sync(0xFFFFFFFFu, acc, o);
        if (lane == 0) s_log[cls] = acc + b2[cls];
    }
    __syncthreads();

    if (tid == 0) {
        const float m  = fmaxf(s_log[0], s_log[1]);
        const float e0 = expf(s_log[0] - m);
        const float e1 = expf(s_log[1] - m);
        const float inv = 1.0f / (e0 + e1);
        out[OUT_PRED_OFF + 0] = e0 * inv;
        out[OUT_PRED_OFF + 1] = e1 * inv;
    }
}

extern "C" void kernel_launch(void* const* d_in, const int* in_sizes, int n_in,
                              void* d_out, int out_size) {
    const int*   tim       = (const int*)  d_in[0];
    const float* X         = (const float*)d_in[1];
    // d_in[2] = X_hap (unused)
    const int*   mask      = (const int*)  d_in[3];
    const int*   last_occ  = (const int*)  d_in[4];
    const float* Ht        = (const float*)d_in[5];
    // d_in[6] = Ct (unused)
    const float* c_t       = (const float*)d_in[7];
    const float* W         = (const float*)d_in[8];
    const float* Bias      = (const float*)d_in[9];
    const float* xTw       = (const float*)d_in[10];
    const float* xTb       = (const float*)d_in[11];
    const float* delTw     = (const float*)d_in[12];
    const float* cinw      = (const float*)d_in[13];
    const float* cfw       = (const float*)d_in[14];
    const float* coutw     = (const float*)d_in[15];
    const float* w1        = (const float*)d_in[16];
    const float* b1        = (const float*)d_in[17];
    const float* w2        = (const float*)d_in[18];
    const float* b2        = (const float*)d_in[19];
    float* out = (float*)d_out;

    const int smem_bytes = NSTAGE * STAGE_B;   // 208896
    cudaFuncSetAttribute(cell_kernel,
                         cudaFuncAttributeMaxDynamicSharedMemorySize, smem_bytes);

    compact_kernel<<<1, 1024>>>(mask);
    cell_kernel<<<GRID_C, 256, smem_bytes>>>(tim, X, mask, last_occ, Ht, c_t,
                                             W, Bias, xTw, xTb, delTw,
                                             cinw, cfw, coutw,
                                             w1, b1, w2, b2, out);
}

// round 14
// speedup vs baseline: 1.0586x; 1.0586x over previous
#include <cuda_runtime.h>
#include <cuda_bf16.h>
#include <math.h>
#include <stdint.h>

#define F_N   10000
#define H_N   64
#define G_N   (4 * H_N)          // 256 gate rows
#define IN_N  (H_N + 1)          // 65
#define W_ELEMS (G_N * IN_N)     // 16640 floats
#define OUT_PRED_OFF 0
#define OUT_H_OFF    2
#define OUT_C_OFF    (2 + F_N * H_N)

#define GRID_C 148
#define NSTAGE 3
#define MAXNF  68                // max features per CTA

// per-stage float offsets (R6 layout — proven fastest)
#define W_OFF     0
#define BIAS_OFF  (W_ELEMS)                  // 16640  (256 floats)
#define HT_OFF    (BIAS_OFF + G_N)           // 16896  (64) -> 16B aligned
#define XTW_OFF   (HT_OFF + H_N)             // 16960
#define XTB_OFF   (XTW_OFF + H_N)            // 17024
#define DELT_OFF  (XTB_OFF + H_N)            // 17088  (128)
#define CIN_OFF   (DELT_OFF + 2 * H_N)       // 17216
#define CF_OFF    (CIN_OFF + H_N)            // 17280
#define COUT_OFF  (CF_OFF + H_N)             // 17344
#define STAGE_F   (COUT_OFF + H_N)           // 17408 floats = 69632 B
#define STAGE_B   (STAGE_F * 4)

__device__ float g_sumC[H_N];    // zero at module load; last CTA re-zeros
__device__ float g_sumH[H_N];
__device__ int   g_cnt;          // total active; written by compact_kernel
__device__ unsigned int g_done;
__device__ int   g_list[F_N];    // compacted active feature indices

__device__ __forceinline__ float sigmoidf_(float x) {
    return 1.0f / (1.0f + expf(-x));
}

__device__ __forceinline__ uint32_t smem_u32(const void* p) {
    uint32_t a;
    asm("{ .reg .u64 t; cvta.to.shared.u64 t, %1; cvt.u32.u64 %0, t; }"
        : "=r"(a) : "l"(p));
    return a;
}

__device__ __forceinline__ void mbar_init(uint32_t mbar, uint32_t cnt) {
    asm volatile("mbarrier.init.shared.b64 [%0], %1;" :: "r"(mbar), "r"(cnt) : "memory");
}
__device__ __forceinline__ void mbar_expect_tx(uint32_t mbar, uint32_t bytes) {
    asm volatile("mbarrier.arrive.expect_tx.shared.b64 _, [%0], %1;"
                 :: "r"(mbar), "r"(bytes) : "memory");
}
__device__ __forceinline__ void mbar_wait(uint32_t mbar, uint32_t parity) {
    uint32_t done;
    asm volatile(
        "{\n\t.reg .pred p;\n\t"
        "mbarrier.try_wait.parity.acquire.cta.shared::cta.b64 p, [%1], %2;\n\t"
        "selp.b32 %0, 1, 0, p;\n\t}"
        : "=r"(done) : "r"(mbar), "r"(parity) : "memory");
    if (!done) {
        asm volatile(
            "{\n\t.reg .pred P1;\n\t"
            "W_%=:\n\t"
            "mbarrier.try_wait.parity.acquire.cta.shared::cta.b64 P1, [%0], %1, 0x989680;\n\t"
            "@P1 bra.uni D_%=;\n\t"
            "bra.uni W_%=;\n\t"
            "D_%=:\n\t}"
            :: "r"(mbar), "r"(parity) : "memory");
    }
}
__device__ __forceinline__ void bulk_cp(uint32_t dst, const void* src,
                                        uint32_t bytes, uint32_t mbar) {
    asm volatile(
        "cp.async.bulk.shared::cta.global.mbarrier::complete_tx::bytes [%0], [%1], %2, [%3];"
        :: "r"(dst), "l"(src), "r"(bytes), "r"(mbar) : "memory");
}
__device__ __forceinline__ void stcs(float* p, float v) {
    asm volatile("st.global.cs.f32 [%0], %1;" :: "l"(p), "f"(v) : "memory");
}

// ---- order-preserving mask compaction: g_list, g_cnt ----
__global__ __launch_bounds__(1024) void compact_kernel(const int* __restrict__ mask) {
    __shared__ int s_cnt[1024];
    const int tid = threadIdx.x;
    const int per = (F_N + 1023) / 1024;      // 10
    const int base = tid * per;
    int idx[10];
    int c = 0;
    #pragma unroll
    for (int i = 0; i < per; i++) {
        const int g = base + i;
        if (g < F_N && mask[g] == 1) idx[c++] = g;
    }
    s_cnt[tid] = c;
    __syncthreads();
    for (int o = 1; o < 1024; o <<= 1) {
        const int v = (tid >= o) ? s_cnt[tid - o] : 0;
        __syncthreads();
        s_cnt[tid] += v;
        __syncthreads();
    }
    const int off = s_cnt[tid] - c;           // exclusive prefix
    for (int i = 0; i < c; i++) g_list[off + i] = idx[i];
    if (tid == 1023) g_cnt = s_cnt[1023];
}

__global__ __launch_bounds__(256, 1) void cell_kernel(
    const int*  __restrict__ tim_p,
    const float* __restrict__ X,
    const int*  __restrict__ mask,
    const int*  __restrict__ last_occ,
    const float* __restrict__ Ht,
    const float* __restrict__ c_t,
    const float* __restrict__ W,       // [F, 256, 65]
    const float* __restrict__ Bias,    // [F, 256]
    const float* __restrict__ xTw,     // [F, 64]
    const float* __restrict__ xTb,     // [F, 64]
    const float* __restrict__ delTw,   // [F, 128]
    const float* __restrict__ cinw,    // [F, 64]
    const float* __restrict__ cfw,     // [F, 64]
    const float* __restrict__ coutw,   // [F, 64]
    const float* __restrict__ w1,      // [128,128]
    const float* __restrict__ b1,      // [128]
    const float* __restrict__ w2,      // [2,128]
    const float* __restrict__ b2,      // [2]
    float* __restrict__ out)
{
    extern __shared__ float s_buf[];           // NSTAGE * STAGE_F floats
    __shared__ float s_gates[G_N];
    __shared__ float s_ct[H_N];
    __shared__ int   s_f[MAXNF];
    __shared__ float s_X[MAXNF];
    __shared__ float s_delta[MAXNF];
    __shared__ __align__(8) uint64_t s_mbar[NSTAGE];
    __shared__ int s_last;

    const int bid = blockIdx.x;
    const int tid = threadIdx.x;
    const int total = g_cnt;                               // from compact_kernel
    const int na = (total > bid) ? ((total - bid - 1) / GRID_C + 1) : 0;

    // ---- prologue: barriers, gather active features, zero inactive rows ----
    if (tid == 0) {
        for (int s = 0; s < NSTAGE; s++) mbar_init(smem_u32(&s_mbar[s]), 1);
        asm volatile("fence.proxy.async.shared::cta;" ::: "memory");
    }
    {
        const int tim = *tim_p;
        if (tid < na) {                                    // na <= 68 < 256
            const int f = g_list[bid + tid * GRID_C];
            s_f[tid]     = f;
            s_X[tid]     = X[f];
            s_delta[tid] = (float)tim - (float)last_occ[f];
        }
    }
    if (tid < H_N) s_ct[tid] = c_t[tid];

    // inactive rows of this CTA's static partition -> zeros (or Ht if total==0)
    {
        const int nf_static = (F_N - bid + GRID_C - 1) / GRID_C;
        if (tid < nf_static) {
            const int f = bid + tid * GRID_C;
            if (mask[f] != 1) {
                float* dst = out + OUT_H_OFF + (size_t)f * H_N;
                if (total == 0) {          // reference fallback: H_curr = Ht
                    const float* src = Ht + (size_t)f * H_N;
                    #pragma unroll
                    for (int q = 0; q < H_N; q++) stcs(&dst[q], src[q]);
                } else {
                    #pragma unroll
                    for (int q = 0; q < H_N; q++) stcs(&dst[q], 0.0f);
                }
            }
        }
    }
    __syncthreads();

    const uint32_t sbase = smem_u32(s_buf);

    auto issue = [&](int j) {
        const int s = j % NSTAGE;
        const size_t f = (size_t)s_f[j];
        const uint32_t d = sbase + (uint32_t)s * STAGE_B;
        const uint32_t mb = smem_u32(&s_mbar[s]);
        mbar_expect_tx(mb, STAGE_B);
        bulk_cp(d + W_OFF * 4,    W     + f * W_ELEMS,   W_ELEMS * 4, mb);
        bulk_cp(d + BIAS_OFF * 4, Bias  + f * G_N,       G_N * 4,     mb);
        bulk_cp(d + HT_OFF * 4,   Ht    + f * H_N,       H_N * 4,     mb);
        bulk_cp(d + XTW_OFF * 4,  xTw   + f * H_N,       H_N * 4,     mb);
        bulk_cp(d + XTB_OFF * 4,  xTb   + f * H_N,       H_N * 4,     mb);
        bulk_cp(d + DELT_OFF * 4, delTw + f * 2 * H_N,   2 * H_N * 4, mb);
        bulk_cp(d + CIN_OFF * 4,  cinw  + f * H_N,       H_N * 4,     mb);
        bulk_cp(d + CF_OFF * 4,   cfw   + f * H_N,       H_N * 4,     mb);
        bulk_cp(d + COUT_OFF * 4, coutw + f * H_N,       H_N * 4,     mb);
    };

    if (tid == 0) {
        const int pre = (na < NSTAGE) ? na : NSTAGE;
        for (int j = 0; j < pre; j++) issue(j);
    }

    // per-thread partial sums (replaces per-iteration global atomics)
    float accC = 0.0f, accH = 0.0f;

    // ---- main loop over ACTIVE features only (R12 structure) ----
    for (int j = 0; j < na; j++) {
        const int s  = j % NSTAGE;
        const int ph = (j / NSTAGE) & 1;
        mbar_wait(smem_u32(&s_mbar[s]), ph);

        const float* buf = s_buf + (size_t)s * STAGE_F;

        // gates: one row/thread; stride-65 conflict-free + float4 broadcasts
        {
            const float  xv  = s_X[j];
            const float* row = buf + tid * IN_N;
            const float4* ht4 = (const float4*)(buf + HT_OFF);
            float acc = row[0] * xv;
            #pragma unroll
            for (int c = 0; c < 16; c++) {
                const float4 h4 = ht4[c];
                acc += row[1 + 4 * c] * h4.x;
                acc += row[2 + 4 * c] * h4.y;
                acc += row[3 + 4 * c] * h4.z;
                acc += row[4 + 4 * c] * h4.w;
            }
            s_gates[tid] = acc + buf[BIAS_OFF + tid];
        }
        __syncthreads();

        if (tid < H_N) {
            const int h = tid;
            const int f = s_f[j];
            const float ct    = s_ct[h];
            const float delta = s_delta[j];

            const float gi     = sigmoidf_(s_gates[h]           + buf[CIN_OFF + h] * ct);
            const float gf     = sigmoidf_(s_gates[H_N + h]     + buf[CF_OFF + h]  * ct);
            const float go_pre = s_gates[2 * H_N + h];
            const float pre_c  = tanhf(s_gates[3 * H_N + h]);

            const float xmT = buf[XTW_OFF + h] * s_X[j] + buf[XTB_OFF + h];
            const float dTt = buf[DELT_OFF + h]        * delta;
            const float dTo = buf[DELT_OFF + H_N + h]  * delta;
            const float Tt  = sigmoidf_(xmT + dTt);

            const float aggc = gf * ct + gi * Tt * pre_c;
            const float go   = sigmoidf_(go_pre + buf[COUT_OFF + h] * aggc + dTo);
            const float hn   = go * tanhf(aggc);

            stcs(&out[OUT_H_OFF + (size_t)f * H_N + h], hn);   // mf == 1 here
            accC += aggc;          // register accumulation — no global atomics
            accH += hn;
        }
        __syncthreads();   // all reads of stage s complete

        if (tid == 0 && j + NSTAGE < na) issue(j + NSTAGE);
    }

    // one atomic pair per thread for the whole CTA (128 ops vs 128*na)
    if (tid < H_N && na > 0) {
        atomicAdd(&g_sumC[tid], accC);
        atomicAdd(&g_sumH[tid], accH);
    }

    // ---- last-CTA-done: fused MLP head ----
    __threadfence();
    if (tid == 0) {
        const unsigned prev = atomicAdd(&g_done, 1u);
        s_last = (prev == GRID_C - 1u) ? 1 : 0;
    }
    __syncthreads();
    if (!s_last) return;
    __threadfence();                    // acquire: see all CTAs' atomics

    // reuse stage smem for head scratch
    float* s_inp  = s_buf;              // 128
    float* s_part = s_buf + 128;        // 256
    float* s_hid  = s_buf + 128 + 256;  // 128
    float* s_log  = s_buf + 128 + 256 + 128; // 2

    const float cnt = fmaxf((float)total, 1.0f);
    if (tid < 2 * H_N) {
        const float v = ((tid < H_N) ? g_sumC[tid] : g_sumH[tid - H_N]) / cnt;
        s_inp[tid] = v;
        if (tid < H_N) out[OUT_C_OFF + tid] = v;
    }
    __syncthreads();

    // re-zero device accumulators for next graph replay
    if (tid < H_N) { g_sumC[tid] = 0.0f; g_sumH[tid] = 0.0f; }
    if (tid == H_N) g_done = 0u;

    // hidden: 2 threads per row, 16 float4 LDGs each
    {
        const int r = tid >> 1;
        const int g = tid & 1;
        const float4* wrow = (const float4*)(w1 + r * 2 * H_N) + g * 16;
        const float4* in4  = (const float4*)s_inp + g * 16;
        float acc = 0.0f;
        #pragma unroll
        for (int q = 0; q < 16; q++) {
            const float4 w4 = wrow[q];
            const float4 i4 = in4[q];
            acc += w4.x * i4.x + w4.y * i4.y + w4.z * i4.z + w4.w * i4.w;
        }
        s_part[tid] = acc;
    }
    __syncthreads();

    if (tid < 2 * H_N)
        s_hid[tid] = fmaxf(s_part[2 * tid] + s_part[2 * tid + 1] + b1[tid], 0.0f);
    __syncthreads();

    // logits: warp 0 -> class 0, warp 1 -> class 1
    if (tid < 64) {
        const int cls  = tid >> 5;
        const int lane = tid & 31;
        const float4 w4a = ((const float4*)(w2 + cls * 2 * H_N))[lane];
        const float* hp = s_hid + lane * 4;
        float acc = w4a.x * hp[0] + w4a.y * hp[1] + w4a.z * hp[2] + w4a.w * hp[3];
        #pragma unroll
        for (int o = 16; o > 0; o >>= 1)
            acc += __shfl_xor_sync(0xFFFFFFFFu, acc, o);
        if (lane == 0) s_log[cls] = acc + b2[cls];
    }
    __syncthreads();

    if (tid == 0) {
        const float m  = fmaxf(s_log[0], s_log[1]);
        const float e0 = expf(s_log[0] - m);
        const float e1 = expf(s_log[1] - m);
        const float inv = 1.0f / (e0 + e1);
        out[OUT_PRED_OFF + 0] = e0 * inv;
        out[OUT_PRED_OFF + 1] = e1 * inv;
    }
}

extern "C" void kernel_launch(void* const* d_in, const int* in_sizes, int n_in,
                              void* d_out, int out_size) {
    const int*   tim       = (const int*)  d_in[0];
    const float* X         = (const float*)d_in[1];
    // d_in[2] = X_hap (unused)
    const int*   mask      = (const int*)  d_in[3];
    const int*   last_occ  = (const int*)  d_in[4];
    const float* Ht        = (const float*)d_in[5];
    // d_in[6] = Ct (unused)
    const float* c_t       = (const float*)d_in[7];
    const float* W         = (const float*)d_in[8];
    const float* Bias      = (const float*)d_in[9];
    const float* xTw       = (const float*)d_in[10];
    const float* xTb       = (const float*)d_in[11];
    const float* delTw     = (const float*)d_in[12];
    const float* cinw      = (const float*)d_in[13];
    const float* cfw       = (const float*)d_in[14];
    const float* coutw     = (const float*)d_in[15];
    const float* w1        = (const float*)d_in[16];
    const float* b1        = (const float*)d_in[17];
    const float* w2        = (const float*)d_in[18];
    const float* b2        = (const float*)d_in[19];
    float* out = (float*)d_out;

    const int smem_bytes = NSTAGE * STAGE_B;   // 208896
    cudaFuncSetAttribute(cell_kernel,
                         cudaFuncAttributeMaxDynamicSharedMemorySize, smem_bytes);

    compact_kernel<<<1, 1024>>>(mask);
    cell_kernel<<<GRID_C, 256, smem_bytes>>>(tim, X, mask, last_occ, Ht, c_t,
                                             W, Bias, xTw, xTb, delTw,
                                             cinw, cfw, coutw,
                                             w1, b1, w2, b2, out);
}